// round 13
// baseline (speedup 1.0000x reference)
#include <cuda_runtime.h>
#include <cstdint>

#define TT     2190
#define NWARM  365
#define NMAIN  1825
#define NG     10000
#define KER    15
#define CH     25
#define BLK    128
#define DPF    12                       // prefetch depth in steps
#define RING   16                       // smem ring slots (power of 2 > DPF)
#define ROWB   (NG * 3 * 4)             // bytes per time row
#define SLOTF  (BLK * 3)                // floats per ring slot

// scratch (device globals: the sanctioned no-alloc workaround)
__device__ float g_q[NMAIN * NG];       // raw simulated discharge, 73 MB
__device__ float g_uh[KER * NG];        // per-cell unit hydrograph

// ---------------------------------------------------------------------------
struct Cell {
    float beta, inv_fc, fc, inv_lpfc, pperc, uzl, tt, cfmax, mcf, cfr, cwh,
          k0, omk1, omk2;
    float sp, mw, sm, suz, slz, sw;
};

__device__ __forceinline__ void cell_init(Cell& c, const float* __restrict__ par, int g)
{
    float raw[14];
    #pragma unroll
    for (int i = 0; i < 14; ++i) raw[i] = par[g * 14 + i];
    c.beta    = 1.0f   + raw[0]  * 5.0f;
    c.fc      = 50.0f  + raw[1]  * 950.0f;
    c.k0      = 0.05f  + raw[2]  * 0.85f;
    float k1  = 0.01f  + raw[3]  * 0.49f;
    float k2  = 0.001f + raw[4]  * 0.199f;
    float lp  = 0.2f   + raw[5]  * 0.8f;
    c.pperc   =          raw[6]  * 10.0f;
    c.uzl     =          raw[7]  * 100.0f;
    c.tt      = -2.5f  + raw[8]  * 5.0f;
    c.cfmax   = 0.5f   + raw[9]  * 9.5f;
    c.cfr     =          raw[10] * 0.1f;
    c.cwh     =          raw[11] * 0.2f;
    c.mcf     = -c.cfmax * c.tt;
    c.inv_fc  = 1.0f / c.fc;
    c.inv_lpfc= 1.0f / (lp * c.fc);
    c.omk1    = 1.0f - k1;
    c.omk2    = 1.0f - k2;
    c.sp = 0.001f; c.mw = 0.001f; c.sm = 0.001f; c.suz = 0.001f; c.slz = 0.001f;
    c.sw = __powf(c.sm * c.inv_fc, c.beta);   // soil wetness of CURRENT sm
}

// one HBV timestep; carried-sw form (sw of pre-update sm, recomputed at end)
__device__ __forceinline__ float step(Cell& c, float precip, float pet, float tm)
{
    float rain = (tm >= c.tt) ? precip : 0.0f;
    float snow = precip - rain;
    float d    = fmaf(c.cfmax, tm, c.mcf);               // cfmax*(tm-tt)
    float sp1  = c.sp + snow;
    float melt = fminf(fmaxf(d, 0.0f), sp1);
    float mw1  = c.mw + melt;
    float cfrd = c.cfr * d;
    float refr = fminf(fmaxf(-cfrd, 0.0f), mw1);         // cfr*cfmax*(tt-tm)
    float mw2  = mw1 - refr;
    float sp2  = sp1 - melt + refr;
    float ts   = fmaxf(fmaf(-c.cwh, sp2, mw2), 0.0f);
    c.mw = mw2 - ts;
    c.sp = sp2;
    float rts  = rain + ts;
    float rech = rts * c.sw;                             // sw <= 1 structurally
    float srts = c.sm + rts;
    float sm1  = srts - rech;
    float sm2  = fminf(sm1, c.fc);
    float exc  = sm1 - sm2;                              // max(sm1-fc,0)
    float pil  = pet * c.inv_lpfc;                       // off sm-chain
    float t2   = fminf(sm2 * pil, pet);                  // pet*clip(ef,0,1)
    c.sm       = fmaxf(sm2 - t2, 1e-5f);                 // sm - min(sm, pet*ef)
    c.sw       = __powf(c.sm * c.inv_fc, c.beta);        // for NEXT step
    float suz2 = c.suz + rech + exc;
    float perc = fminf(suz2, c.pperc);
    float suz3 = suz2 - perc;
    float q0   = c.k0 * fmaxf(suz3 - c.uzl, 0.0f);
    float suzn = (suz3 - q0) * c.omk1;                   // q0+q1 = suz3 - suzn
    float slz1 = c.slz + perc;
    float slzn = slz1 * c.omk2;                          // q2 = slz1 - slzn
    c.suz = suzn;
    c.slz = slzn;
    return (suz3 - suzn) + (slz1 - slzn);
}

// ---------------------------------------------------------------------------
__device__ __forceinline__ void cp4(uint32_t dst, const char* src)
{
    asm volatile("cp.async.ca.shared.global [%0], [%1], 4;"
                 :: "r"(dst), "l"(src));
}
__device__ __forceinline__ void cp_commit()
{
    asm volatile("cp.async.commit_group;");
}
__device__ __forceinline__ void cp_wait_keep10()
{
    asm volatile("cp.async.wait_group 10;");   // slots n and n+1 resident
}

// ---------------------------------------------------------------------------
// K0: gamma unit hydrograph per cell (standalone — R12 showed folding it
// into the scan costs more in scan register pressure than the launch saves)
// ---------------------------------------------------------------------------
__global__ void __launch_bounds__(256)
uh_kernel(const float* __restrict__ par)
{
    int g = blockIdx.x * blockDim.x + threadIdx.x;
    if (g >= NG) return;
    float a   = fmaf(par[g * 14 + 12], 2.9f, 0.1f);
    float th  = fmaf(par[g * 14 + 13], 6.5f, 0.5f);
    float am1 = a - 1.0f;
    float ith = 1.0f / th;

    float w[KER], s = 0.0f;
    #pragma unroll
    for (int k = 0; k < KER; ++k) {
        float tk = (float)k + 0.5f;
        w[k] = __expf(fmaf(am1, __logf(tk), -tk * ith));
        s += w[k];
    }
    float inv = 1.0f / s;
    #pragma unroll
    for (int k = 0; k < KER; ++k) g_uh[k * NG + g] = w[k] * inv;
}

// ---------------------------------------------------------------------------
// K1: sequential HBV scan — the R9 kernel VERBATIM (best: 194.4us).
// ---------------------------------------------------------------------------
__global__ void __launch_bounds__(128, 1)
hbv_scan_kernel(const float* __restrict__ x, const float* __restrict__ par)
{
    __shared__ float ring[RING * SLOTF];

    int tid = threadIdx.x;
    int g   = blockIdx.x * BLK + tid;
    bool active = (g < NG);
    int gc  = active ? g : (NG - 1);    // clamp for param read

    Cell c;
    cell_init(c, par, gc);

    uint32_t sb = (uint32_t)__cvta_generic_to_shared(ring) + (uint32_t)tid * 12u;
    const float* __restrict__ myr = ring + tid * 3;

    const char* src = (const char*)x + (size_t)g * 12u;

    // ---- prologue: prefetch steps 0..DPF-1, then stage step 0 in registers ----
    #pragma unroll
    for (int s = 0; s < DPF; ++s) {
        uint32_t dst = sb + (uint32_t)s * (SLOTF * 4);
        if (active) { cp4(dst, src); cp4(dst + 4, src + 4); cp4(dst + 8, src + 8); }
        cp_commit();
        src += ROWB;
    }
    asm volatile("cp.async.wait_group 11;");     // slot 0 resident
    float sp_ = myr[0], se_ = myr[1], st_ = myr[2];

    int rd = 0;           // ring slot of current step
    int wr = DPF;         // ring slot being filled

    // ---- warmup: 365 steps, copies unconditional (last target step 376) ----
    #pragma unroll 1
    for (int it = 0; it < NWARM / 5; ++it) {
        #pragma unroll
        for (int u = 0; u < 5; ++u) {
            cp_wait_keep10();                    // slots rd and rd+1 resident
            int nb = ((rd + 1) & (RING - 1)) * SLOTF;
            float np = myr[nb + 0];
            float ne = myr[nb + 1];
            float nt = myr[nb + 2];
            uint32_t dst = sb + (uint32_t)wr * (SLOTF * 4);
            if (active) { cp4(dst, src); cp4(dst + 4, src + 4); cp4(dst + 8, src + 8); }
            cp_commit();
            src += ROWB;
            rd = (rd + 1) & (RING - 1);
            wr = (wr + 1) & (RING - 1);
            (void)step(c, sp_, se_, st_);
            sp_ = np; se_ = ne; st_ = nt;
        }
    }

    // ---- main: 1825 steps, copies guarded near the end of the series ----
    float* __restrict__ qp = g_q + g;
    int ncpy = NWARM + DPF;                      // next copy target step
    #pragma unroll 1
    for (int it = 0; it < NMAIN / 5; ++it) {
        #pragma unroll
        for (int u = 0; u < 5; ++u) {
            cp_wait_keep10();
            int nb = ((rd + 1) & (RING - 1)) * SLOTF;
            float np = myr[nb + 0];              // step-(n+1) inputs (last
            float ne = myr[nb + 1];              // iteration reads stale smem,
            float nt = myr[nb + 2];              // values never consumed)
            uint32_t dst = sb + (uint32_t)wr * (SLOTF * 4);
            if (active && ncpy < TT) { cp4(dst, src); cp4(dst + 4, src + 4); cp4(dst + 8, src + 8); }
            cp_commit();                          // empty groups keep FIFO depth
            src += ROWB;
            ncpy++;
            rd = (rd + 1) & (RING - 1);
            wr = (wr + 1) & (RING - 1);
            float q = step(c, sp_, se_, st_);
            sp_ = np; se_ = ne; st_ = nt;
            if (active) *qp = q;
            qp += NG;
        }
    }
    asm volatile("cp.async.wait_group 0;");      // drain before exit
}

// ---------------------------------------------------------------------------
// K2: 15-tap causal convolution, restructured for MLP: all 39 input rows
// (14 history + 25 current) are loaded in one front batch (independent LDGs,
// MLP~39), then 25x15 FMAs, then 25 batched stores. No per-iteration
// load->shift dependency chain.
// ---------------------------------------------------------------------------
__global__ void __launch_bounds__(256)
conv_kernel(float* __restrict__ out)
{
    int g = blockIdx.x * blockDim.x + threadIdx.x;
    if (g >= NG) return;
    int t0 = blockIdx.y * CH;

    // front-batched loads: v[j] = q[t0 - (KER-1) + j], zero-padded for t<0
    float v[KER - 1 + CH];
    #pragma unroll
    for (int j = 0; j < KER - 1; ++j) {
        int t = t0 - (KER - 1) + j;
        v[j] = (t >= 0) ? g_q[t * NG + g] : 0.0f;
    }
    #pragma unroll
    for (int j = 0; j < CH; ++j)
        v[KER - 1 + j] = g_q[(t0 + j) * NG + g];

    float uh[KER];
    #pragma unroll
    for (int k = 0; k < KER; ++k) uh[k] = g_uh[k * NG + g];

    float o[CH];
    #pragma unroll
    for (int s = 0; s < CH; ++s) {
        float acc = uh[0] * v[KER - 1 + s];
        #pragma unroll
        for (int k = 1; k < KER; ++k)
            acc = fmaf(uh[k], v[KER - 1 + s - k], acc);
        o[s] = acc;
    }

    #pragma unroll
    for (int s = 0; s < CH; ++s)
        out[(t0 + s) * NG + g] = o[s];
}

// ---------------------------------------------------------------------------
extern "C" void kernel_launch(void* const* d_in, const int* in_sizes, int n_in,
                              void* d_out, int out_size)
{
    const float* x   = (const float*)d_in[0];   // (2190, 10000, 3) f32
    const float* par = (const float*)d_in[1];   // (10000, 14) f32
    float*       out = (float*)d_out;           // (1825, 10000, 1) f32

    uh_kernel<<<(NG + 255) / 256, 256>>>(par);
    hbv_scan_kernel<<<(NG + BLK - 1) / BLK, BLK>>>(x, par);
    conv_kernel<<<dim3((NG + 255) / 256, NMAIN / CH), 256>>>(out);
}

// round 15
// speedup vs baseline: 1.5416x; 1.5416x over previous
#include <cuda_runtime.h>
#include <cstdint>

#define TT     2190
#define NWARM  365
#define NMAIN  1825
#define NG     10000
#define KER    15
#define CH     25
#define BLK    128
#define DPF    12                       // prefetch depth in steps
#define RING   16                       // smem ring slots (power of 2 > DPF)
#define ROWB   (NG * 3 * 4)             // bytes per time row
#define SLOTF  (BLK * 3)                // floats per ring slot

// scratch (device globals: the sanctioned no-alloc workaround)
__device__ float g_q[NMAIN * NG];       // raw simulated discharge, 73 MB
__device__ float g_uh[KER * NG];        // per-cell unit hydrograph

// ---------------------------------------------------------------------------
struct Cell {
    float beta, inv_fc, fc, inv_lpfc, pperc, uzl, tt, cfmax, mcf, cfr, cwh,
          k0, omk1, omk2;
    float sp, mw, sm, suz, slz, sw;
};

__device__ __forceinline__ void cell_init(Cell& c, const float* __restrict__ par, int g)
{
    float raw[14];
    #pragma unroll
    for (int i = 0; i < 14; ++i) raw[i] = par[g * 14 + i];
    c.beta    = 1.0f   + raw[0]  * 5.0f;
    c.fc      = 50.0f  + raw[1]  * 950.0f;
    c.k0      = 0.05f  + raw[2]  * 0.85f;
    float k1  = 0.01f  + raw[3]  * 0.49f;
    float k2  = 0.001f + raw[4]  * 0.199f;
    float lp  = 0.2f   + raw[5]  * 0.8f;
    c.pperc   =          raw[6]  * 10.0f;
    c.uzl     =          raw[7]  * 100.0f;
    c.tt      = -2.5f  + raw[8]  * 5.0f;
    c.cfmax   = 0.5f   + raw[9]  * 9.5f;
    c.cfr     =          raw[10] * 0.1f;
    c.cwh     =          raw[11] * 0.2f;
    c.mcf     = -c.cfmax * c.tt;
    c.inv_fc  = 1.0f / c.fc;
    c.inv_lpfc= 1.0f / (lp * c.fc);
    c.omk1    = 1.0f - k1;
    c.omk2    = 1.0f - k2;
    c.sp = 0.001f; c.mw = 0.001f; c.sm = 0.001f; c.suz = 0.001f; c.slz = 0.001f;
    c.sw = __powf(c.sm * c.inv_fc, c.beta);   // soil wetness of CURRENT sm
}

// one HBV timestep; carried-sw form (sw of pre-update sm, recomputed at end)
__device__ __forceinline__ float step(Cell& c, float precip, float pet, float tm)
{
    float rain = (tm >= c.tt) ? precip : 0.0f;
    float snow = precip - rain;
    float d    = fmaf(c.cfmax, tm, c.mcf);               // cfmax*(tm-tt)
    float sp1  = c.sp + snow;
    float melt = fminf(fmaxf(d, 0.0f), sp1);
    float mw1  = c.mw + melt;
    float cfrd = c.cfr * d;
    float refr = fminf(fmaxf(-cfrd, 0.0f), mw1);         // cfr*cfmax*(tt-tm)
    float mw2  = mw1 - refr;
    float sp2  = sp1 - melt + refr;
    float ts   = fmaxf(fmaf(-c.cwh, sp2, mw2), 0.0f);
    c.mw = mw2 - ts;
    c.sp = sp2;
    float rts  = rain + ts;
    float rech = rts * c.sw;                             // sw <= 1 structurally
    float srts = c.sm + rts;
    float sm1  = srts - rech;
    float sm2  = fminf(sm1, c.fc);
    float exc  = sm1 - sm2;                              // max(sm1-fc,0)
    float pil  = pet * c.inv_lpfc;                       // off sm-chain
    float t2   = fminf(sm2 * pil, pet);                  // pet*clip(ef,0,1)
    c.sm       = fmaxf(sm2 - t2, 1e-5f);                 // sm - min(sm, pet*ef)
    c.sw       = __powf(c.sm * c.inv_fc, c.beta);        // for NEXT step
    float suz2 = c.suz + rech + exc;
    float perc = fminf(suz2, c.pperc);
    float suz3 = suz2 - perc;
    float q0   = c.k0 * fmaxf(suz3 - c.uzl, 0.0f);
    float suzn = (suz3 - q0) * c.omk1;                   // q0+q1 = suz3 - suzn
    float slz1 = c.slz + perc;
    float slzn = slz1 * c.omk2;                          // q2 = slz1 - slzn
    c.suz = suzn;
    c.slz = slzn;
    return (suz3 - suzn) + (slz1 - slzn);
}

// ---------------------------------------------------------------------------
__device__ __forceinline__ void cp4(uint32_t dst, const char* src)
{
    asm volatile("cp.async.ca.shared.global [%0], [%1], 4;"
                 :: "r"(dst), "l"(src));
}
__device__ __forceinline__ void cp_commit()
{
    asm volatile("cp.async.commit_group;");
}
__device__ __forceinline__ void cp_wait_keep10()
{
    asm volatile("cp.async.wait_group 10;");   // slots n and n+1 resident
}

// ---------------------------------------------------------------------------
// K0: gamma unit hydrograph per cell
// ---------------------------------------------------------------------------
__global__ void __launch_bounds__(256)
uh_kernel(const float* __restrict__ par)
{
    int g = blockIdx.x * blockDim.x + threadIdx.x;
    if (g >= NG) return;
    float a   = fmaf(par[g * 14 + 12], 2.9f, 0.1f);
    float th  = fmaf(par[g * 14 + 13], 6.5f, 0.5f);
    float am1 = a - 1.0f;
    float ith = 1.0f / th;

    float w[KER], s = 0.0f;
    #pragma unroll
    for (int k = 0; k < KER; ++k) {
        float tk = (float)k + 0.5f;
        w[k] = __expf(fmaf(am1, __logf(tk), -tk * ith));
        s += w[k];
    }
    float inv = 1.0f / s;
    #pragma unroll
    for (int k = 0; k < KER; ++k) g_uh[k * NG + g] = w[k] * inv;
}

// ---------------------------------------------------------------------------
// K1: sequential HBV scan — R9 skeleton (self-produce/self-consume cp.async
// ring, per-step commit, register-staged next-step inputs) with ONE change:
// the main loop is split exactly so copies are unconditional and in-bounds
// (targets 377..2189), followed by a copy-free 12-step drain tail.
// ---------------------------------------------------------------------------
__global__ void __launch_bounds__(128, 1)
hbv_scan_kernel(const float* __restrict__ x, const float* __restrict__ par)
{
    __shared__ float ring[RING * SLOTF];

    int tid = threadIdx.x;
    int g   = blockIdx.x * BLK + tid;
    bool active = (g < NG);
    int gc  = active ? g : (NG - 1);    // clamp for param read

    Cell c;
    cell_init(c, par, gc);

    uint32_t sb = (uint32_t)__cvta_generic_to_shared(ring) + (uint32_t)tid * 12u;
    const float* __restrict__ myr = ring + tid * 3;

    const char* src = (const char*)x + (size_t)g * 12u;

    // ---- prologue: prefetch steps 0..DPF-1, then stage step 0 in registers ----
    #pragma unroll
    for (int s = 0; s < DPF; ++s) {
        uint32_t dst = sb + (uint32_t)s * (SLOTF * 4);
        if (active) { cp4(dst, src); cp4(dst + 4, src + 4); cp4(dst + 8, src + 8); }
        cp_commit();
        src += ROWB;
    }
    asm volatile("cp.async.wait_group 11;");     // slot 0 resident
    float sp_ = myr[0], se_ = myr[1], st_ = myr[2];

    int rd = 0;           // ring slot of current step
    int wr = DPF;         // ring slot being filled

    // ---- warmup: 365 steps, copy targets 12..376 ----
    #pragma unroll 1
    for (int it = 0; it < NWARM / 5; ++it) {
        #pragma unroll
        for (int u = 0; u < 5; ++u) {
            cp_wait_keep10();                    // slots rd and rd+1 resident
            int nb = ((rd + 1) & (RING - 1)) * SLOTF;
            float np = myr[nb + 0];
            float ne = myr[nb + 1];
            float nt = myr[nb + 2];
            uint32_t dst = sb + (uint32_t)wr * (SLOTF * 4);
            if (active) { cp4(dst, src); cp4(dst + 4, src + 4); cp4(dst + 8, src + 8); }
            cp_commit();
            src += ROWB;
            rd = (rd + 1) & (RING - 1);
            wr = (wr + 1) & (RING - 1);
            (void)step(c, sp_, se_, st_);
            sp_ = np; se_ = ne; st_ = nt;
        }
    }

    float* __restrict__ qp = g_q + g;

    // ---- main A: 1810 steps (362 x 5), unconditional copies (targets 377..2186) ----
    #pragma unroll 1
    for (int it = 0; it < 362; ++it) {
        #pragma unroll
        for (int u = 0; u < 5; ++u) {
            cp_wait_keep10();
            int nb = ((rd + 1) & (RING - 1)) * SLOTF;
            float np = myr[nb + 0];
            float ne = myr[nb + 1];
            float nt = myr[nb + 2];
            uint32_t dst = sb + (uint32_t)wr * (SLOTF * 4);
            if (active) { cp4(dst, src); cp4(dst + 4, src + 4); cp4(dst + 8, src + 8); }
            cp_commit();
            src += ROWB;
            rd = (rd + 1) & (RING - 1);
            wr = (wr + 1) & (RING - 1);
            float q = step(c, sp_, se_, st_);
            sp_ = np; se_ = ne; st_ = nt;
            if (active) *qp = q;
            qp += NG;
        }
    }

    // ---- main A': 3 more steps with copies (targets 2187..2189) ----
    #pragma unroll
    for (int u = 0; u < 3; ++u) {
        cp_wait_keep10();
        int nb = ((rd + 1) & (RING - 1)) * SLOTF;
        float np = myr[nb + 0];
        float ne = myr[nb + 1];
        float nt = myr[nb + 2];
        uint32_t dst = sb + (uint32_t)wr * (SLOTF * 4);
        if (active) { cp4(dst, src); cp4(dst + 4, src + 4); cp4(dst + 8, src + 8); }
        cp_commit();
        src += ROWB;
        rd = (rd + 1) & (RING - 1);
        wr = (wr + 1) & (RING - 1);
        float q = step(c, sp_, se_, st_);
        sp_ = np; se_ = ne; st_ = nt;
        if (active) *qp = q;
        qp += NG;
    }

    // ---- drain tail: 12 steps, no copies/commits/waits (all slots resident) ----
    asm volatile("cp.async.wait_group 0;");
    #pragma unroll
    for (int u = 0; u < DPF; ++u) {
        int nb = ((rd + 1) & (RING - 1)) * SLOTF;
        float np = myr[nb + 0];                  // last stage reads stale smem,
        float ne = myr[nb + 1];                  // value never consumed
        float nt = myr[nb + 2];
        rd = (rd + 1) & (RING - 1);
        float q = step(c, sp_, se_, st_);
        sp_ = np; se_ = ne; st_ = nt;
        if (active) *qp = q;
        qp += NG;
    }
}

// ---------------------------------------------------------------------------
// K2: 15-tap causal convolution — the proven R5 shift-register version.
// ---------------------------------------------------------------------------
__global__ void __launch_bounds__(256)
conv_kernel(float* __restrict__ out)
{
    int g = blockIdx.x * blockDim.x + threadIdx.x;
    if (g >= NG) return;
    int t0 = blockIdx.y * CH;

    float uh[KER];
    #pragma unroll
    for (int k = 0; k < KER; ++k) uh[k] = g_uh[k * NG + g];

    float w[KER - 1];
    #pragma unroll
    for (int j = 0; j < KER - 1; ++j) {
        int t = t0 - 1 - j;
        w[j] = (t >= 0) ? g_q[t * NG + g] : 0.0f;
    }

    #pragma unroll
    for (int s = 0; s < CH; ++s) {
        float qn = g_q[(t0 + s) * NG + g];
        float o  = uh[0] * qn;
        #pragma unroll
        for (int j = 0; j < KER - 1; ++j)
            o = fmaf(uh[j + 1], w[j], o);
        out[(t0 + s) * NG + g] = o;
        #pragma unroll
        for (int j = KER - 2; j > 0; --j) w[j] = w[j - 1];
        w[0] = qn;
    }
}

// ---------------------------------------------------------------------------
extern "C" void kernel_launch(void* const* d_in, const int* in_sizes, int n_in,
                              void* d_out, int out_size)
{
    const float* x   = (const float*)d_in[0];   // (2190, 10000, 3) f32
    const float* par = (const float*)d_in[1];   // (10000, 14) f32
    float*       out = (float*)d_out;           // (1825, 10000, 1) f32

    uh_kernel<<<(NG + 255) / 256, 256>>>(par);
    hbv_scan_kernel<<<(NG + BLK - 1) / BLK, BLK>>>(x, par);
    conv_kernel<<<dim3((NG + 255) / 256, NMAIN / CH), 256>>>(out);
}

// round 16
// speedup vs baseline: 1.5712x; 1.0192x over previous
#include <cuda_runtime.h>
#include <cstdint>

#define TT     2190
#define NWARM  365
#define NMAIN  1825
#define NG     10000
#define KER    15
#define CH     25
#define BLK    128
#define DPF    12                       // prefetch depth in steps
#define RING   16                       // smem ring slots (power of 2 > DPF)
#define ROWB   (NG * 3 * 4)             // bytes per time row
#define SLOTF  (BLK * 3)                // floats per ring slot

// scratch (device globals: the sanctioned no-alloc workaround)
__device__ float g_q[NMAIN * NG];       // raw simulated discharge, 73 MB
__device__ float g_uh[KER * NG];        // per-cell unit hydrograph

// ---------------------------------------------------------------------------
struct Cell {
    float beta, inv_fc, fc, inv_lpfc, pperc, nk0uzl, tt, cfmax, mcf, cfr, cwh,
          k0, omk1, omk2;
    float sp, mw, sm, suz, slz, sw;
};

__device__ __forceinline__ void cell_init(Cell& c, const float* __restrict__ par, int g)
{
    float raw[14];
    #pragma unroll
    for (int i = 0; i < 14; ++i) raw[i] = par[g * 14 + i];
    c.beta    = 1.0f   + raw[0]  * 5.0f;
    c.fc      = 50.0f  + raw[1]  * 950.0f;
    c.k0      = 0.05f  + raw[2]  * 0.85f;
    float k1  = 0.01f  + raw[3]  * 0.49f;
    float k2  = 0.001f + raw[4]  * 0.199f;
    float lp  = 0.2f   + raw[5]  * 0.8f;
    c.pperc   =          raw[6]  * 10.0f;
    float uzl =          raw[7]  * 100.0f;
    c.tt      = -2.5f  + raw[8]  * 5.0f;
    c.cfmax   = 0.5f   + raw[9]  * 9.5f;
    c.cfr     =          raw[10] * 0.1f;
    c.cwh     =          raw[11] * 0.2f;
    c.mcf     = -c.cfmax * c.tt;
    c.nk0uzl  = -c.k0 * uzl;
    c.inv_fc  = 1.0f / c.fc;
    c.inv_lpfc= 1.0f / (lp * c.fc);
    c.omk1    = 1.0f - k1;
    c.omk2    = 1.0f - k2;
    c.sp = 0.001f; c.mw = 0.001f; c.sm = 0.001f; c.suz = 0.001f; c.slz = 0.001f;
    c.sw = __powf(c.sm * c.inv_fc, c.beta);   // soil wetness of CURRENT sm
}

// one HBV timestep — chain-minimized form.
//  * snow bucket: net flux f = melt - refreeze (exactly one nonzero):
//      f = min(max(e, -mw), sp1),  e = (tm>=tt) ? d : cfr*d   [exact]
//  * soil: suz + rech + exc == max(suz + rts*sw, (suz+sm+rts) - fc)   [exact]
//  * upper zone: suz3 = max(suz2 - pperc, 0) [exact dual of min];
//      q0 = max(k0*suz3 - k0*uzl, 0) (k0>0, fma form)
//  * carried sw = (sm/fc)^beta of current sm, recomputed at end
__device__ __forceinline__ float step(Cell& c, float precip, float pet, float tm)
{
    // ---- input-only terms (hoistable into previous step's bubbles) ----
    bool  P    = (tm >= c.tt);
    float rain = P ? precip : 0.0f;
    float snow = P ? 0.0f : precip;
    float d    = fmaf(c.cfmax, tm, c.mcf);       // cfmax*(tm-tt)
    float e    = P ? d : c.cfr * d;              // melt(+) / -refreeze(-)
    float pil  = pet * c.inv_lpfc;

    // ---- snow bucket ----
    float sp1  = c.sp + snow;
    float f    = fminf(fmaxf(e, -c.mw), sp1);    // net melt flux
    float sp2  = sp1 - f;
    float mw2  = c.mw + f;
    float ts   = fmaxf(fmaf(-c.cwh, sp2, mw2), 0.0f);
    c.mw = mw2 - ts;
    c.sp = sp2;

    // ---- soil ----
    float rts  = rain + ts;
    float srts = c.sm + rts;
    float suzz = c.suz + srts;
    float a1   = fmaf(rts, c.sw, c.suz);         // suz + recharge
    float sm1  = fmaf(-rts, c.sw, srts);         // sm + rts - recharge
    float suz2 = fmaxf(a1, suzz - c.fc);         // suz + recharge + excess
    float sm2  = fminf(sm1, c.fc);
    float t2   = fminf(sm2 * pil, pet);          // pet*clip(ef,0,1)
    c.sm       = fmaxf(sm2 - t2, 1e-5f);
    c.sw       = __powf(c.sm * c.inv_fc, c.beta);    // for NEXT step

    // ---- upper / lower zones ----
    float suz3 = fmaxf(suz2 - c.pperc, 0.0f);
    float perc = suz2 - suz3;
    float q0   = fmaxf(fmaf(c.k0, suz3, c.nk0uzl), 0.0f);
    float suz4 = suz3 - q0;
    float suzn = suz4 * c.omk1;                  // q0+q1 = suz3 - suzn
    float slz1 = c.slz + perc;
    float slzn = slz1 * c.omk2;                  // q2 = slz1 - slzn
    c.suz = suzn;
    c.slz = slzn;
    return (suz3 - suzn) + (slz1 - slzn);
}

// ---------------------------------------------------------------------------
__device__ __forceinline__ void cp4(uint32_t dst, const char* src)
{
    asm volatile("cp.async.ca.shared.global [%0], [%1], 4;"
                 :: "r"(dst), "l"(src));
}
__device__ __forceinline__ void cp_commit()
{
    asm volatile("cp.async.commit_group;");
}
__device__ __forceinline__ void cp_wait_keep10()
{
    asm volatile("cp.async.wait_group 10;");   // slots n and n+1 resident
}

// ---------------------------------------------------------------------------
// K0: gamma unit hydrograph per cell
// ---------------------------------------------------------------------------
__global__ void __launch_bounds__(256)
uh_kernel(const float* __restrict__ par)
{
    int g = blockIdx.x * blockDim.x + threadIdx.x;
    if (g >= NG) return;
    float a   = fmaf(par[g * 14 + 12], 2.9f, 0.1f);
    float th  = fmaf(par[g * 14 + 13], 6.5f, 0.5f);
    float am1 = a - 1.0f;
    float ith = 1.0f / th;

    float w[KER], s = 0.0f;
    #pragma unroll
    for (int k = 0; k < KER; ++k) {
        float tk = (float)k + 0.5f;
        w[k] = __expf(fmaf(am1, __logf(tk), -tk * ith));
        s += w[k];
    }
    float inv = 1.0f / s;
    #pragma unroll
    for (int k = 0; k < KER; ++k) g_uh[k * NG + g] = w[k] * inv;
}

// ---------------------------------------------------------------------------
// K1: sequential HBV scan — the R9 skeleton VERBATIM (proven best) with the
// chain-minimized step() above.
// ---------------------------------------------------------------------------
__global__ void __launch_bounds__(128, 1)
hbv_scan_kernel(const float* __restrict__ x, const float* __restrict__ par)
{
    __shared__ float ring[RING * SLOTF];

    int tid = threadIdx.x;
    int g   = blockIdx.x * BLK + tid;
    bool active = (g < NG);
    int gc  = active ? g : (NG - 1);    // clamp for param read

    Cell c;
    cell_init(c, par, gc);

    uint32_t sb = (uint32_t)__cvta_generic_to_shared(ring) + (uint32_t)tid * 12u;
    const float* __restrict__ myr = ring + tid * 3;

    const char* src = (const char*)x + (size_t)g * 12u;

    // ---- prologue: prefetch steps 0..DPF-1, then stage step 0 in registers ----
    #pragma unroll
    for (int s = 0; s < DPF; ++s) {
        uint32_t dst = sb + (uint32_t)s * (SLOTF * 4);
        if (active) { cp4(dst, src); cp4(dst + 4, src + 4); cp4(dst + 8, src + 8); }
        cp_commit();
        src += ROWB;
    }
    asm volatile("cp.async.wait_group 11;");     // slot 0 resident
    float sp_ = myr[0], se_ = myr[1], st_ = myr[2];

    int rd = 0;           // ring slot of current step
    int wr = DPF;         // ring slot being filled

    // ---- warmup: 365 steps, copies unconditional (last target step 376) ----
    #pragma unroll 1
    for (int it = 0; it < NWARM / 5; ++it) {
        #pragma unroll
        for (int u = 0; u < 5; ++u) {
            cp_wait_keep10();                    // slots rd and rd+1 resident
            int nb = ((rd + 1) & (RING - 1)) * SLOTF;
            float np = myr[nb + 0];
            float ne = myr[nb + 1];
            float nt = myr[nb + 2];
            uint32_t dst = sb + (uint32_t)wr * (SLOTF * 4);
            if (active) { cp4(dst, src); cp4(dst + 4, src + 4); cp4(dst + 8, src + 8); }
            cp_commit();
            src += ROWB;
            rd = (rd + 1) & (RING - 1);
            wr = (wr + 1) & (RING - 1);
            (void)step(c, sp_, se_, st_);
            sp_ = np; se_ = ne; st_ = nt;
        }
    }

    // ---- main: 1825 steps, copies guarded near the end of the series ----
    float* __restrict__ qp = g_q + g;
    int ncpy = NWARM + DPF;                      // next copy target step
    #pragma unroll 1
    for (int it = 0; it < NMAIN / 5; ++it) {
        #pragma unroll
        for (int u = 0; u < 5; ++u) {
            cp_wait_keep10();
            int nb = ((rd + 1) & (RING - 1)) * SLOTF;
            float np = myr[nb + 0];              // step-(n+1) inputs (last
            float ne = myr[nb + 1];              // iteration reads stale smem,
            float nt = myr[nb + 2];              // values never consumed)
            uint32_t dst = sb + (uint32_t)wr * (SLOTF * 4);
            if (active && ncpy < TT) { cp4(dst, src); cp4(dst + 4, src + 4); cp4(dst + 8, src + 8); }
            cp_commit();                          // empty groups keep FIFO depth
            src += ROWB;
            ncpy++;
            rd = (rd + 1) & (RING - 1);
            wr = (wr + 1) & (RING - 1);
            float q = step(c, sp_, se_, st_);
            sp_ = np; se_ = ne; st_ = nt;
            if (active) *qp = q;
            qp += NG;
        }
    }
    asm volatile("cp.async.wait_group 0;");      // drain before exit
}

// ---------------------------------------------------------------------------
// K2: 15-tap causal convolution — the proven R5 shift-register version.
// ---------------------------------------------------------------------------
__global__ void __launch_bounds__(256)
conv_kernel(float* __restrict__ out)
{
    int g = blockIdx.x * blockDim.x + threadIdx.x;
    if (g >= NG) return;
    int t0 = blockIdx.y * CH;

    float uh[KER];
    #pragma unroll
    for (int k = 0; k < KER; ++k) uh[k] = g_uh[k * NG + g];

    float w[KER - 1];
    #pragma unroll
    for (int j = 0; j < KER - 1; ++j) {
        int t = t0 - 1 - j;
        w[j] = (t >= 0) ? g_q[t * NG + g] : 0.0f;
    }

    #pragma unroll
    for (int s = 0; s < CH; ++s) {
        float qn = g_q[(t0 + s) * NG + g];
        float o  = uh[0] * qn;
        #pragma unroll
        for (int j = 0; j < KER - 1; ++j)
            o = fmaf(uh[j + 1], w[j], o);
        out[(t0 + s) * NG + g] = o;
        #pragma unroll
        for (int j = KER - 2; j > 0; --j) w[j] = w[j - 1];
        w[0] = qn;
    }
}

// ---------------------------------------------------------------------------
extern "C" void kernel_launch(void* const* d_in, const int* in_sizes, int n_in,
                              void* d_out, int out_size)
{
    const float* x   = (const float*)d_in[0];   // (2190, 10000, 3) f32
    const float* par = (const float*)d_in[1];   // (10000, 14) f32
    float*       out = (float*)d_out;           // (1825, 10000, 1) f32

    uh_kernel<<<(NG + 255) / 256, 256>>>(par);
    hbv_scan_kernel<<<(NG + BLK - 1) / BLK, BLK>>>(x, par);
    conv_kernel<<<dim3((NG + 255) / 256, NMAIN / CH), 256>>>(out);
}